// round 17
// baseline (speedup 1.0000x reference)
#include <cuda_runtime.h>
#include <cuda_fp16.h>
#include <math.h>
#include <stdint.h>

#define BATCH 4
#define SEQ   4096
#define DMODEL 2048
#define HD    128
#define DV    256
#define MROWS (BATCH*SEQ)

// packed-fp16 planes (word = 2 adjacent elements, low half = even index)
__device__ uint32_t g_Qh[MROWS * 128];                       // Q hi (scaled)
__device__ uint32_t g_Kh[MROWS * 128];                       // K hi
__device__ uint32_t g_Vh[MROWS * 128];                       // V hi
__device__ uint32_t g_xh[MROWS * 1024], g_xl[MROWS * 1024];  // x hi/lo
__device__ uint32_t g_WH[3 * DMODEL * 128];                  // W hi [z][k][npair]

// ---------------------------------------------------------------------------
// helpers
// ---------------------------------------------------------------------------
__device__ __forceinline__ void mma_f16(float c[4], const uint32_t a[4], const uint32_t b[2]) {
    asm volatile(
        "mma.sync.aligned.m16n8k16.row.col.f32.f16.f16.f32 "
        "{%0,%1,%2,%3}, {%4,%5,%6,%7}, {%8,%9}, {%0,%1,%2,%3};"
        : "+f"(c[0]), "+f"(c[1]), "+f"(c[2]), "+f"(c[3])
        : "r"(a[0]), "r"(a[1]), "r"(a[2]), "r"(a[3]), "r"(b[0]), "r"(b[1]));
}
__device__ __forceinline__ uint32_t pack2h(float e0, float e1) {
    __half2 hv = __floats2half2_rn(e0, e1);
    return *reinterpret_cast<uint32_t*>(&hv);
}
__device__ __forceinline__ void packsplit(float e0, float e1, uint32_t& h, uint32_t& lo) {
    __half2 hv = __floats2half2_rn(e0, e1);
    h = *reinterpret_cast<uint32_t*>(&hv);
    float2 bk = __half22float2(hv);
    __half2 lv = __floats2half2_rn(e0 - bk.x, e1 - bk.y);
    lo = *reinterpret_cast<uint32_t*>(&lv);
}
__device__ __forceinline__ float ex2f(float x) {
    float r;
    asm("ex2.approx.f32 %0, %1;" : "=f"(r) : "f"(x));
    return r;
}
__device__ __forceinline__ uint32_t cvta_shared(const void* p) {
    uint32_t a;
    asm("{ .reg .u64 t; cvta.to.shared.u64 t, %1; cvt.u32.u64 %0, t; }" : "=r"(a) : "l"(p));
    return a;
}
#define CP_ASYNC16(dst, src) \
    asm volatile("cp.async.cg.shared.global [%0], [%1], 16;" :: "r"(dst), "l"(src))
#define CP_COMMIT() asm volatile("cp.async.commit_group;" ::: "memory")
#define CP_WAIT1()  asm volatile("cp.async.wait_group 1;" ::: "memory")
#define CP_WAIT0()  asm volatile("cp.async.wait_group 0;" ::: "memory")
#define LDSM4(r0, r1, r2, r3, addr) \
    asm volatile("ldmatrix.sync.aligned.m8n8.x4.shared.b16 {%0,%1,%2,%3}, [%4];" \
        : "=r"(r0), "=r"(r1), "=r"(r2), "=r"(r3) : "r"(addr))
#define LDSM4T(r0, r1, r2, r3, addr) \
    asm volatile("ldmatrix.sync.aligned.m8n8.x4.trans.shared.b16 {%0,%1,%2,%3}, [%4];" \
        : "=r"(r0), "=r"(r1), "=r"(r2), "=r"(r3) : "r"(addr))
// swizzled byte offset of 16B chunk c within a 512B row r
#define SWZ(c, r) ((((c) & 24) | (((c) ^ (r)) & 7)) << 4)

// ---------------------------------------------------------------------------
// Kernel 0a/0b: pack x (hi+lo) and W (hi) to fp16 planes
// ---------------------------------------------------------------------------
__global__ __launch_bounds__(256) void pack_x_kernel(const float* __restrict__ x) {
    size_t t = (size_t)blockIdx.x * 256 + threadIdx.x;
    float4 v = *(const float4*)&x[t * 4];
    uint32_t h0, l0, h1, l1;
    packsplit(v.x, v.y, h0, l0);
    packsplit(v.z, v.w, h1, l1);
    *(uint2*)&g_xh[t * 2] = make_uint2(h0, h1);
    *(uint2*)&g_xl[t * 2] = make_uint2(l0, l1);
}
__global__ __launch_bounds__(256) void pack_w_kernel(
    const float* __restrict__ WQ, const float* __restrict__ WK,
    const float* __restrict__ WV)
{
    size_t t = (size_t)blockIdx.x * 256 + threadIdx.x;
    int z = (int)(t / (DMODEL * 64));
    size_t r = t % (DMODEL * 64);
    const float* W = (z == 0) ? WQ : (z == 1) ? WK : WV;
    float4 v = *(const float4*)&W[r * 4];
    size_t o = (size_t)z * (DMODEL * 128) + r * 2;
    *(uint2*)&g_WH[o] = make_uint2(pack2h(v.x, v.y), pack2h(v.z, v.w));
}

// ---------------------------------------------------------------------------
// Kernel 1: projection GEMM, fp16 2-term ((xh+xl)*Wh).
// 2-DEEP cp.async pipeline: two copy groups in flight; wait_group 1
// gives a full iteration of latency tolerance per chunk.
// ldmatrix (A non-trans, W trans). CTA 128m x 128n; 8 warps; BK=32.
// ---------------------------------------------------------------------------
#define PJ_AW 36                     // A pitch words (144B %128==16)
#define PJ_BW 68                     // B pitch words (272B %128==16)
#define PJ_ABUF (128*PJ_AW)          // 4608 per plane
#define PJ_BBUF (32*PJ_BW)           // 2176
#define PJ_HALF (2*PJ_ABUF + PJ_BBUF)     // 11392 words
#define PJ_SMEM_BYTES (2 * PJ_HALF * 4)   // 91136 -> 2 CTAs/SM
#define PJ_NCH (DMODEL / 32)              // 64 chunks

__global__ __launch_bounds__(256, 2) void proj_mma_kernel(void)
{
    extern __shared__ uint32_t pw[];
    const uint32_t smbase = cvta_shared(pw);
    const int tid = threadIdx.x;
    const int w   = tid >> 5, l = tid & 31;
    const int gid = l >> 2,  tig = l & 3;
    const int wr  = w >> 1,  wc  = w & 1;
    const int z   = blockIdx.x % 3;            // weight select
    const int n0w = (blockIdx.x / 3) * 64;     // word offset of n-block
    const int m0c = blockIdx.y * 128;          // m-block (slow dim)
    const uint32_t* __restrict__ WHp = g_WH + (size_t)z * (DMODEL * 128);

    const int rsa = ((l >> 3) & 1) * 8 + (l & 7);
    const int bsa = (l >> 4) * 16;

    float acc[2][8][4];
#pragma unroll
    for (int mb = 0; mb < 2; mb++)
#pragma unroll
        for (int nb = 0; nb < 8; nb++)
#pragma unroll
            for (int i = 0; i < 4; i++) acc[mb][nb][i] = 0.f;

#define PJ_STAGE(c, buf) do {                                                   \
        uint32_t base = smbase + (uint32_t)(buf) * (PJ_HALF * 4);               \
        _Pragma("unroll")                                                       \
        for (int it = 0; it < 4; it++) {                                        \
            int idx = it * 256 + tid;                                           \
            int plane = idx >> 9;                                               \
            int i2 = idx & 511;                                                 \
            int r = i2 >> 2, q = (i2 & 3) * 4;                                  \
            const uint32_t* src = (plane ? g_xl : g_xh)                         \
                + (size_t)(m0c + r) * 1024 + (c) * 16 + q;                      \
            CP_ASYNC16(base + (plane * PJ_ABUF + r * PJ_AW + q) * 4, src);      \
        }                                                                       \
        _Pragma("unroll")                                                       \
        for (int it = 0; it < 2; it++) {                                        \
            int idx = it * 256 + tid;                                           \
            int r = idx >> 4, q = (idx & 15) * 4;                               \
            const uint32_t* src = WHp + (size_t)((c) * 32 + r) * 128 + n0w + q; \
            CP_ASYNC16(base + (2 * PJ_ABUF + r * PJ_BW + q) * 4, src);          \
        }                                                                       \
        CP_COMMIT();                                                            \
    } while (0)

    // prime 2 stages
    PJ_STAGE(0, 0);
    PJ_STAGE(1, 1);

    const uint32_t aRow = (uint32_t)(((wr * 32 + rsa) * PJ_AW) * 4 + bsa);
    const uint32_t bRow = (uint32_t)((rsa * PJ_BW) * 4 + wc * 128 + bsa);

    for (int c = 0; c < PJ_NCH; c++) {
        int buf = c & 1;
        CP_WAIT1();            // group(c) complete; group(c+1) still in flight
        __syncthreads();       // all warps see buf data

        uint32_t hbase = smbase + (uint32_t)buf * (PJ_HALF * 4);
#pragma unroll
        for (int kk = 0; kk < 2; kk++) {
            uint32_t ah[2][4], al[2][4];
#pragma unroll
            for (int mb = 0; mb < 2; mb++) {
                uint32_t Ab = hbase + aRow + (uint32_t)(mb * (16 * PJ_AW * 4) + kk * 32);
                LDSM4(ah[mb][0], ah[mb][1], ah[mb][2], ah[mb][3], Ab);
                LDSM4(al[mb][0], al[mb][1], al[mb][2], al[mb][3], Ab + PJ_ABUF * 4);
            }
#pragma unroll
            for (int nq = 0; nq < 4; nq++) {
                uint32_t Bb = hbase + (2 * PJ_ABUF) * 4 + bRow
                            + (uint32_t)(kk * (16 * PJ_BW * 4) + nq * 32);
                uint32_t bh0, bh1, bh2, bh3;
                LDSM4T(bh0, bh1, bh2, bh3, Bb);
                uint32_t BH0[2] = {bh0, bh1};
                uint32_t BH1[2] = {bh2, bh3};
#pragma unroll
                for (int mb = 0; mb < 2; mb++) {
                    mma_f16(acc[mb][nq * 2],     ah[mb], BH0);
                    mma_f16(acc[mb][nq * 2],     al[mb], BH0);
                    mma_f16(acc[mb][nq * 2 + 1], ah[mb], BH1);
                    mma_f16(acc[mb][nq * 2 + 1], al[mb], BH1);
                }
            }
        }
        __syncthreads();       // all warps done reading buf
        if (c + 2 < PJ_NCH) PJ_STAGE(c + 2, buf);
    }
#undef PJ_STAGE

    // epilogue: single-plane fp16 outputs; Q folds HD^-0.5 * log2(e)
    const float qscale = 0.08838834764831845f * 1.4426950408889634f;
    uint32_t* Gh = (z == 0) ? g_Qh : (z == 1) ? g_Kh : g_Vh;
    const float s = (z == 0) ? qscale : 1.f;
#pragma unroll
    for (int mb = 0; mb < 2; mb++) {
        int r0 = m0c + wr * 32 + mb * 16 + gid;
#pragma unroll
        for (int nb = 0; nb < 8; nb++) {
            int cw = n0w + wc * 32 + nb * 4 + tig;
            Gh[(size_t)r0 * 128 + cw]       = pack2h(acc[mb][nb][0] * s, acc[mb][nb][1] * s);
            Gh[(size_t)(r0 + 8) * 128 + cw] = pack2h(acc[mb][nb][2] * s, acc[mb][nb][3] * s);
        }
    }
}

// ---------------------------------------------------------------------------
// Kernel 2: flash differential attention (VERBATIM R15/R16 — 471us).
// fp16, QK 1-term, PV 2-term, ABN=64, swizzled tiles, no-max ex2 softmax.
// ---------------------------------------------------------------------------
#define ABM 32
#define ABN 64
#define ATHR 256
#define SPP 132   // P pitch words (528B %128==16)

#define SQ  0                      // 32 x 128 swizzled (Q hi)
#define SK  4096                   // 64 x 128 swizzled (K hi)
#define SV  12288                  // 64 x 128 swizzled (V hi)
#define SP  20480                  // 32 x 132: [m0 hi32|m0 lo32|m1 hi32|m1 lo32|pad]
#define SLR 24704                  // 128
#define SLAM 24832
#define ATOT 24836
#define ATOT_BYTES (ATOT * 4)      // 99344 B -> 2 CTAs/SM

__global__ __launch_bounds__(ATHR, 2) void diff_attn_mma(
    const float* __restrict__ lq1, const float* __restrict__ lq2,
    const float* __restrict__ lk1, const float* __restrict__ lk2,
    float* __restrict__ out)
{
    extern __shared__ float sm[];
    uint32_t* smw = (uint32_t*)sm;
    const uint32_t smbase = cvta_shared(sm);
    const int tid = threadIdx.x;
    const int w   = tid >> 5, l = tid & 31;
    const int gid = l >> 2,  tig = l & 3;
    const int b   = blockIdx.y;
    const int q0  = blockIdx.x * ABM;

    // issue K(0), V(0)
    {
#pragma unroll
        for (int it = 0; it < 8; it++) {
            int idx = it * ATHR + tid;
            int r = idx >> 5, c = idx & 31;
            const uint32_t* src = g_Kh + (size_t)(b * SEQ + r) * 128 + c * 4;
            CP_ASYNC16(smbase + SK * 4 + r * 512 + SWZ(c, r), src);
        }
        CP_COMMIT();
#pragma unroll
        for (int it = 0; it < 8; it++) {
            int idx = it * ATHR + tid;
            int r = idx >> 5, c = idx & 31;
            const uint32_t* src = g_Vh + (size_t)(b * SEQ + r) * 128 + c * 4;
            CP_ASYNC16(smbase + SV * 4 + r * 512 + SWZ(c, r), src);
        }
        CP_COMMIT();
    }

    // lambda scalar
    if (tid < 32) {
        float s1 = 0.f, s2 = 0.f;
        for (int i = l; i < HD; i += 32) {
            s1 += lq1[i] * lk1[i];
            s2 += lq2[i] * lk2[i];
        }
#pragma unroll
        for (int o = 16; o; o >>= 1) {
            s1 += __shfl_xor_sync(0xffffffffu, s1, o);
            s2 += __shfl_xor_sync(0xffffffffu, s2, o);
        }
        if (l == 0) {
            double li = 0.8 - 0.6 * exp(-3.6);
            sm[SLAM] = __expf(s1) + __expf(s2) + (float)li;
        }
    }

    // Q stage (swizzled)
#pragma unroll
    for (int it = 0; it < 4; it++) {
        int idx = it * ATHR + tid;
        int r = idx >> 5, c = idx & 31;
        uint4 v = *(const uint4*)(g_Qh + (size_t)(b * SEQ + q0 + r) * 128 + c * 4);
        *(uint4*)((char*)sm + r * 512 + SWZ(c, r)) = v;
    }

    // warp roles
    const int mat = w >> 2;
    const int wl  = w & 3;
    const int qk_m = wl >> 1;
    const int qk_n = wl & 1;
    const int pv_m = w >> 2;
    const int qd   = wl;

    // ldmatrix lane address components
    const int rsa = ((l >> 3) & 1) * 8 + (l & 7);
    const int bsa = (l >> 4) * 16;
    const int rsb = (l >> 4) * 8 + (l & 7);
    const int bsb = ((l >> 3) & 1) * 16;
    const int xa  = (rsa & 7) * 16;
    const int xb  = (rsb & 7) * 16;

    const uint32_t qA  = smbase + (qk_m * 16 + rsa) * 512 + mat * 256;
    const uint32_t kB0 = smbase + SK * 4 + (qk_n * 32 + rsb) * 512 + mat * 256;
    const uint32_t kB1 = kB0 + 16 * 512;
    const uint32_t vB  = smbase + SV * 4 + rsa * 512 + qd * 128;
    const uint32_t pA0 = smbase + SP * 4 + (pv_m * 16 + rsa) * (SPP * 4) + bsa;
    const uint32_t pA1 = pA0 + 256;

    float O[2][8][4];
#pragma unroll
    for (int mt = 0; mt < 2; mt++)
#pragma unroll
        for (int nt = 0; nt < 8; nt++)
#pragma unroll
            for (int i = 0; i < 4; i++) O[mt][nt][i] = 0.f;

    float lacc0 = 0.f, lacc1 = 0.f;

    for (int j0 = 0; j0 < SEQ; j0 += ABN) {
        CP_WAIT1();        // K(j) arrived
        __syncthreads();   // B1

        // QK^T (1-term) + ex2 + pack(h/l) + STS P + l accumulate
        {
            float c[4][4];
#pragma unroll
            for (int nb = 0; nb < 4; nb++)
#pragma unroll
                for (int i = 0; i < 4; i++) c[nb][i] = 0.f;
#pragma unroll
            for (int kk = 0; kk < 8; kk++) {
                uint32_t a0, a1, a2, a3;
                LDSM4(a0, a1, a2, a3, qA + ((kk * 32 + bsa) ^ xa));
                uint32_t ah[4] = {a0, a1, a2, a3};
                uint32_t k0, k1, k2, k3, k4, k5, k6, k7;
                int offb = (kk * 32 + bsb) ^ xb;
                LDSM4(k0, k1, k2, k3, kB0 + offb);
                LDSM4(k4, k5, k6, k7, kB1 + offb);
                uint32_t b0[2] = {k0, k1}, b1[2] = {k2, k3};
                uint32_t b2[2] = {k4, k5}, b3[2] = {k6, k7};
                mma_f16(c[0], ah, b0);
                mma_f16(c[1], ah, b1);
                mma_f16(c[2], ah, b2);
                mma_f16(c[3], ah, b3);
            }
            float e[4][4];
#pragma unroll
            for (int nb = 0; nb < 4; nb++)
#pragma unroll
                for (int i = 0; i < 4; i++) e[nb][i] = ex2f(c[nb][i]);
#pragma unroll
            for (int nb = 0; nb < 4; nb++) {
                lacc0 += e[nb][0] + e[nb][1];
                lacc1 += e[nb][2] + e[nb][3];
            }
            int rowa = SP + (qk_m * 16 + gid) * SPP + mat * 64 + qk_n * 16 + tig;
            int rowb = rowa + 8 * SPP;
#pragma unroll
            for (int nb = 0; nb < 4; nb++) {
                uint32_t h, lo;
                packsplit(e[nb][0], e[nb][1], h, lo);
                smw[rowa + nb * 4]      = h;
                smw[rowa + nb * 4 + 32] = lo;
                packsplit(e[nb][2], e[nb][3], h, lo);
                smw[rowb + nb * 4]      = h;
                smw[rowb + nb * 4 + 32] = lo;
            }
        }
        CP_WAIT0();        // V(j) arrived
        __syncthreads();   // B2: P ready, V visible, K(j) dead

        // issue K(j+1)
        {
            int jj = j0 + ABN;
            if (jj >= SEQ) jj = 0;
#pragma unroll
            for (int it = 0; it < 8; it++) {
                int idx = it * ATHR + tid;
                int r = idx >> 5, c = idx & 31;
                const uint32_t* src = g_Kh + (size_t)(b * SEQ + jj + r) * 128 + c * 4;
                CP_ASYNC16(smbase + SK * 4 + r * 512 + SWZ(c, r), src);
            }
            CP_COMMIT();
        }

        // PV: warp = m16 x 64 cols, BOTH mats; P(h+l) x Vh (2-term)
        {
#pragma unroll
            for (int kk = 0; kk < 4; kk++) {
                uint32_t P0h[4], P0l[4], P1h[4], P1l[4];
                LDSM4(P0h[0], P0h[1], P0h[2], P0h[3], pA0 + kk * 32);
                LDSM4(P0l[0], P0l[1], P0l[2], P0l[3], pA0 + kk * 32 + 128);
                LDSM4(P1h[0], P1h[1], P1h[2], P1h[3], pA1 + kk * 32);
                LDSM4(P1l[0], P1l[1], P1l[2], P1l[3], pA1 + kk * 32 + 128);
                uint32_t vrow = vB + kk * 8192;
#pragma unroll
                for (int q = 0; q < 4; q++) {
                    uint32_t vh0, vh1, vh2, vh3;
                    LDSM4T(vh0, vh1, vh2, vh3, vrow + (((q * 32 + bsa) ^ xa)));
                    uint32_t B0[2] = {vh0, vh1}, B1[2] = {vh2, vh3};
                    mma_f16(O[0][2 * q],     P0h, B0);
                    mma_f16(O[0][2 * q],     P0l, B0);
                    mma_f16(O[0][2 * q + 1], P0h, B1);
                    mma_f16(O[0][2 * q + 1], P0l, B1);
                    mma_f16(O[1][2 * q],     P1h, B0);
                    mma_f16(O[1][2 * q],     P1l, B0);
                    mma_f16(O[1][2 * q + 1], P1h, B1);
                    mma_f16(O[1][2 * q + 1], P1l, B1);
                }
            }
        }
        __syncthreads();   // B3: PV done; V(j), P(j) dead

        // issue V(j+1)
        {
            int jj = j0 + ABN;
            if (jj >= SEQ) jj = 0;
#pragma unroll
            for (int it = 0; it < 8; it++) {
                int idx = it * ATHR + tid;
                int r = idx >> 5, c = idx & 31;
                const uint32_t* src = g_Vh + (size_t)(b * SEQ + jj + r) * 128 + c * 4;
                CP_ASYNC16(smbase + SV * 4 + r * 512 + SWZ(c, r), src);
            }
            CP_COMMIT();
        }
    }
    CP_WAIT0();

    // publish l partials: [qk_n][mat*32 + row]
    {
        float t0 = lacc0, t1 = lacc1;
        t0 += __shfl_xor_sync(0xffffffffu, t0, 1);
        t0 += __shfl_xor_sync(0xffffffffu, t0, 2);
        t1 += __shfl_xor_sync(0xffffffffu, t1, 1);
        t1 += __shfl_xor_sync(0xffffffffu, t1, 2);
        if (tig == 0) {
            int base = SLR + qk_n * 64 + mat * 32 + qk_m * 16 + gid;
            sm[base]     = t0;
            sm[base + 8] = t1;
        }
    }
    __syncthreads();

    // epilogue: direct in-register combine (warp holds O1 and O2)
    {
        const float lam = sm[SLAM];
        const int ra = pv_m * 16 + gid, rb = ra + 8;
        float l1a = sm[SLR + ra] + sm[SLR + 64 + ra];
        float l2a = sm[SLR + 32 + ra] + sm[SLR + 96 + ra];
        float l1b = sm[SLR + rb] + sm[SLR + 64 + rb];
        float l2b = sm[SLR + 32 + rb] + sm[SLR + 96 + rb];
        float i1a = 1.f / l1a, s2a = lam / l2a;
        float i1b = 1.f / l1b, s2b = lam / l2b;
        size_t basea = (size_t)(b * SEQ + q0 + ra) * DV;
        size_t baseb = (size_t)(b * SEQ + q0 + rb) * DV;
#pragma unroll
        for (int nt = 0; nt < 8; nt++) {
            int cc = qd * 64 + nt * 8 + 2 * tig;
            *(float2*)&out[basea + cc] =
                make_float2(O[0][nt][0] * i1a - O[1][nt][0] * s2a,
                            O[0][nt][1] * i1a - O[1][nt][1] * s2a);
            *(float2*)&out[baseb + cc] =
                make_float2(O[0][nt][2] * i1b - O[1][nt][2] * s2b,
                            O[0][nt][3] * i1b - O[1][nt][3] * s2b);
        }
    }
}

// ---------------------------------------------------------------------------
// Launch
// ---------------------------------------------------------------------------
extern "C" void kernel_launch(void* const* d_in, const int* in_sizes, int n_in,
                              void* d_out, int out_size)
{
    const float* x   = (const float*)d_in[0];
    const float* WQ  = (const float*)d_in[1];
    const float* WK  = (const float*)d_in[2];
    const float* WV  = (const float*)d_in[3];
    const float* lq1 = (const float*)d_in[4];
    const float* lq2 = (const float*)d_in[5];
    const float* lk1 = (const float*)d_in[6];
    const float* lk2 = (const float*)d_in[7];
    float* out = (float*)d_out;

    pack_x_kernel<<<(MROWS * DMODEL / 4) / 256, 256>>>(x);
    pack_w_kernel<<<(3 * DMODEL * DV / 4) / 256, 256>>>(WQ, WK, WV);

    cudaFuncSetAttribute(proj_mma_kernel,
                         cudaFuncAttributeMaxDynamicSharedMemorySize, PJ_SMEM_BYTES);
    dim3 pgrid(6, MROWS / 128);
    proj_mma_kernel<<<pgrid, 256, PJ_SMEM_BYTES>>>();

    cudaFuncSetAttribute(diff_attn_mma,
                         cudaFuncAttributeMaxDynamicSharedMemorySize, ATOT_BYTES);
    dim3 agrid(SEQ / ABM, BATCH);
    diff_attn_mma<<<agrid, ATHR, ATOT_BYTES>>>(lq1, lq2, lk1, lk2, out);
}